// round 6
// baseline (speedup 1.0000x reference)
#include <cuda_runtime.h>
#include <cstdint>

#define MD   128
#define NH   8
#define DV   16
#define NMAX 50000
#define EMAX 1600000
#define EPSF 1e-12f
#define CAP  256

// ---------------- scratch (static device allocations; no cudaMalloc) --------
__device__ float g_value[(size_t)NMAX * MD];   // [N,128] value projection
__device__ float g_vsrc[NMAX * NH];            // [N,8]
__device__ float g_vtgt[NMAX * NH];            // [N,8]
__device__ int   g_cnt[NMAX];                  // in-degree histogram
__device__ int   g_off[NMAX + 1];              // CSR offsets (exclusive scan)
__device__ int   g_cursor[NMAX];               // scatter cursors
__device__ int   g_csr_src[EMAX];              // src node per CSR slot
__device__ int   g_csr_eid[EMAX];              // original edge id per CSR slot
__device__ float g_gmax;                       // global max of leaky_relu scores

__device__ __forceinline__ void atomicMaxF(float* addr, float v) {
    int old = __float_as_int(*addr);
    while (__int_as_float(old) < v) {
        int assumed = old;
        old = atomicCAS((int*)addr, assumed, __float_as_int(v));
        if (old == assumed) break;
    }
}

// ---------------- K0: reset per-launch state --------------------------------
__global__ void k_init(int N) {
    int i = blockIdx.x * blockDim.x + threadIdx.x;
    if (i < N) g_cnt[i] = 0;
    if (i == 0) g_gmax = -1e30f;
}

// ---------------- K1: node projections (value, vsrc/vtgt, self+bias) --------
// block = 128 threads, each block handles TM=16 nodes; thread j owns output col j.
__global__ void k_node(const float* __restrict__ inp,
                       const float* __restrict__ Wv,
                       const float* __restrict__ ws,
                       const float* __restrict__ wt,
                       const float* __restrict__ Wself,
                       const float* __restrict__ bias,
                       float* __restrict__ out, int N) {
    const int TM = 16;
    __shared__ float A[TM][MD];
    int n0  = blockIdx.x * TM;
    int tid = threadIdx.x;

    for (int idx = tid; idx < TM * MD; idx += 128) {
        int m = idx >> 7, k = idx & 127;
        int n = n0 + m;
        A[m][k] = (n < N) ? inp[(size_t)n * MD + k] : 0.f;
    }
    __syncthreads();

    const int j = tid;
    float wsj = ws[j], wtj = wt[j];

    float acc[TM];
#pragma unroll
    for (int m = 0; m < TM; m++) acc[m] = 0.f;
    for (int kt = 0; kt < MD; kt += 16) {
        float wk[16];
#pragma unroll
        for (int kk = 0; kk < 16; kk++) wk[kk] = Wv[j * MD + kt + kk];
#pragma unroll
        for (int m = 0; m < TM; m++) {
#pragma unroll
            for (int kk = 0; kk < 16; kk++) acc[m] += A[m][kt + kk] * wk[kk];
        }
    }
    int h = j >> 4, d = j & 15;
#pragma unroll
    for (int m = 0; m < TM; m++) {
        int n = n0 + m;
        float v = acc[m];
        if (n < N) g_value[(size_t)n * MD + j] = v;
        float t1 = v * wsj;
        float t2 = v * wtj;
#pragma unroll
        for (int o = 8; o > 0; o >>= 1) {
            t1 += __shfl_xor_sync(0xffffffffu, t1, o);
            t2 += __shfl_xor_sync(0xffffffffu, t2, o);
        }
        if (d == 0 && n < N) {
            g_vsrc[n * NH + h] = t1;
            g_vtgt[n * NH + h] = t2;
        }
    }

    // self projection
#pragma unroll
    for (int m = 0; m < TM; m++) acc[m] = 0.f;
    for (int kt = 0; kt < MD; kt += 16) {
        float wk[16];
#pragma unroll
        for (int kk = 0; kk < 16; kk++) wk[kk] = Wself[j * MD + kt + kk];
#pragma unroll
        for (int m = 0; m < TM; m++) {
#pragma unroll
            for (int kk = 0; kk < 16; kk++) acc[m] += A[m][kt + kk] * wk[kk];
        }
    }
    float b = bias[j];
#pragma unroll
    for (int m = 0; m < TM; m++) {
        int n = n0 + m;
        if (n < N) out[(size_t)n * MD + j] = acc[m] + b;
    }
}

// ---------------- K2: in-degree histogram + global score max ----------------
__global__ void k_edge_hist_max(const int* __restrict__ ei, int E) {
    int tid = threadIdx.x;
    float m = -1e30f;
    for (int e = blockIdx.x * blockDim.x + tid; e < E; e += gridDim.x * blockDim.x) {
        int s = ei[e];
        int t = ei[E + e];
        atomicAdd(&g_cnt[t], 1);
        const float4* vs4 = (const float4*)g_vsrc;
        const float4* vt4 = (const float4*)g_vtgt;
        float4 a0 = vs4[s * 2], a1 = vs4[s * 2 + 1];
        float4 b0 = vt4[t * 2], b1 = vt4[t * 2 + 1];
        float va[8] = {a0.x, a0.y, a0.z, a0.w, a1.x, a1.y, a1.z, a1.w};
        float vb[8] = {b0.x, b0.y, b0.z, b0.w, b1.x, b1.y, b1.z, b1.w};
#pragma unroll
        for (int hh = 0; hh < 8; hh++) {
            float sc = va[hh] + vb[hh];
            sc = sc > 0.f ? sc : 0.2f * sc;   // leaky_relu(0.2)
            m = fmaxf(m, sc);
        }
    }
    __shared__ float red[256];
    red[tid] = m;
    __syncthreads();
    for (int o = 128; o > 0; o >>= 1) {
        if (tid < o) red[tid] = fmaxf(red[tid], red[tid + o]);
        __syncthreads();
    }
    if (tid == 0) atomicMaxF(&g_gmax, red[0]);
}

// ---------------- K3: exclusive scan of g_cnt -> g_off, g_cursor ------------
__global__ void k_scan(int N) {
    __shared__ int sh[1024];
    __shared__ int s_run;
    int tid = threadIdx.x;
    if (tid == 0) s_run = 0;
    __syncthreads();
    for (int base = 0; base < N; base += 1024) {
        int i = base + tid;
        int v = (i < N) ? g_cnt[i] : 0;
        sh[tid] = v;
        __syncthreads();
        for (int o = 1; o < 1024; o <<= 1) {
            int t = (tid >= o) ? sh[tid - o] : 0;
            __syncthreads();
            sh[tid] += t;
            __syncthreads();
        }
        int run  = s_run;
        int excl = sh[tid] - v;
        if (i < N) {
            g_off[i]    = run + excl;
            g_cursor[i] = run + excl;
        }
        __syncthreads();
        if (tid == 1023) s_run = run + sh[1023];
        __syncthreads();
    }
    if (tid == 0) g_off[N] = s_run;
}

// ---------------- K4: scatter edges into CSR --------------------------------
__global__ void k_scatter(const int* __restrict__ ei, int E) {
    for (int e = blockIdx.x * blockDim.x + threadIdx.x; e < E;
         e += gridDim.x * blockDim.x) {
        int s = ei[e];
        int t = ei[E + e];
        int p = atomicAdd(&g_cursor[t], 1);
        g_csr_src[p] = s;
        g_csr_eid[p] = e;
    }
}

// ---------------- K5: per-target softmax + renorm + aggregation -------------
// One block (128 threads) per target node. No float atomics anywhere.
__global__ void k_aggregate(const float* __restrict__ dist,
                            float* __restrict__ out,
                            float* __restrict__ attn_out,
                            int N) {
    int n   = blockIdx.x;
    int tid = threadIdx.x;
    int base = g_off[n];
    int deg  = g_off[n + 1] - base;
    if (deg == 0) return;

    __shared__ float s_vtgt[NH];
    __shared__ float s_den[NH], s_asum[NH];
    __shared__ float s_part[128];
    __shared__ float s_exp[CAP * NH];
    __shared__ int   s_src[CAP], s_eid[CAP];
    __shared__ int   t_src[CAP], t_eid[CAP];
    __shared__ float s_dist[CAP];

    if (tid < NH) s_vtgt[tid] = g_vtgt[n * NH + tid];
    float gm = g_gmax;
    int h  = tid & 7;    // head owned in (edge,head)-strided loops (stride 128)
    int hc = tid >> 4;   // head of this output column

    if (deg <= CAP) {
        for (int i = tid; i < deg; i += 128) {
            s_src[i] = g_csr_src[base + i];
            s_eid[i] = g_csr_eid[base + i];
        }
        __syncthreads();
        // deterministic rank-sort by original edge id (ids unique)
        for (int i = tid; i < deg; i += 128) {
            int key = s_eid[i];
            int r = 0;
            for (int q = 0; q < deg; q++) r += (s_eid[q] < key);
            t_eid[r] = key;
            t_src[r] = s_src[i];
        }
        __syncthreads();
        for (int i = tid; i < deg; i += 128) s_dist[i] = dist[t_eid[i]];
        __syncthreads();

        // exp(leaky_relu(score) - gmax), per (edge,head)
        float dloc = 0.f;
        for (int idx = tid; idx < deg * NH; idx += 128) {
            int e = idx >> 3;
            float s = g_vsrc[t_src[e] * NH + h] + s_vtgt[h];
            s = s > 0.f ? s : 0.2f * s;
            float ex = __expf(s - gm);
            s_exp[idx] = ex;
            dloc += ex;
        }
        s_part[tid] = dloc;
        __syncthreads();
        if (tid < NH) {
            float v = 0.f;
#pragma unroll
            for (int k = 0; k < 16; k++) v += s_part[tid + 8 * k];
            s_den[tid] = v;
        }
        __syncthreads();

        // attn1 = exp/(denom+eps)/dist ; accumulate per-head sum
        float aloc = 0.f;
        for (int idx = tid; idx < deg * NH; idx += 128) {
            int e = idx >> 3;
            float a = s_exp[idx] / (s_den[h] + EPSF) / s_dist[e];
            s_exp[idx] = a;
            aloc += a;
        }
        s_part[tid] = aloc;
        __syncthreads();
        if (tid < NH) {
            float v = 0.f;
#pragma unroll
            for (int k = 0; k < 16; k++) v += s_part[tid + 8 * k];
            s_asum[tid] = v;
        }
        __syncthreads();

        // final attn; write to attn output at original edge position
        for (int idx = tid; idx < deg * NH; idx += 128) {
            int e = idx >> 3;
            float a = s_exp[idx] / s_asum[h];
            s_exp[idx] = a;
            if (attn_out) attn_out[(size_t)t_eid[e] * NH + h] = a;
        }
        __syncthreads();

        // weighted aggregation: thread tid = output column (h=tid>>4,d=tid&15)
        float acc = 0.f;
#pragma unroll 4
        for (int e = 0; e < deg; e++)
            acc += s_exp[e * NH + hc] * g_value[(size_t)t_src[e] * MD + tid];
        out[(size_t)n * MD + tid] += acc;
    } else {
        // ---- fallback (deg > CAP): chunked with recompute; correctness path ----
        __syncthreads();
        float dloc = 0.f;
        for (int idx = tid; idx < deg * NH; idx += 128) {
            int e = idx >> 3;
            int sn = g_csr_src[base + e];
            float s = g_vsrc[sn * NH + h] + s_vtgt[h];
            s = s > 0.f ? s : 0.2f * s;
            dloc += __expf(s - gm);
        }
        s_part[tid] = dloc;
        __syncthreads();
        if (tid < NH) {
            float v = 0.f;
            for (int k = 0; k < 16; k++) v += s_part[tid + 8 * k];
            s_den[tid] = v;
        }
        __syncthreads();
        float aloc = 0.f;
        for (int idx = tid; idx < deg * NH; idx += 128) {
            int e = idx >> 3;
            int sn = g_csr_src[base + e];
            float s = g_vsrc[sn * NH + h] + s_vtgt[h];
            s = s > 0.f ? s : 0.2f * s;
            float a = __expf(s - gm) / (s_den[h] + EPSF) / dist[g_csr_eid[base + e]];
            aloc += a;
        }
        s_part[tid] = aloc;
        __syncthreads();
        if (tid < NH) {
            float v = 0.f;
            for (int k = 0; k < 16; k++) v += s_part[tid + 8 * k];
            s_asum[tid] = v;
        }
        __syncthreads();
        float acc = 0.f;
        for (int c0 = 0; c0 < deg; c0 += CAP) {
            int clen = min(CAP, deg - c0);
            for (int i = tid; i < clen; i += 128) {
                t_src[i] = g_csr_src[base + c0 + i];
                t_eid[i] = g_csr_eid[base + c0 + i];
            }
            __syncthreads();
            for (int i = tid; i < clen; i += 128) s_dist[i] = dist[t_eid[i]];
            __syncthreads();
            for (int idx = tid; idx < clen * NH; idx += 128) {
                int e = idx >> 3;
                float s = g_vsrc[t_src[e] * NH + h] + s_vtgt[h];
                s = s > 0.f ? s : 0.2f * s;
                float a = __expf(s - gm) / (s_den[h] + EPSF) / s_dist[e] / s_asum[h];
                s_exp[idx] = a;
                if (attn_out) attn_out[(size_t)t_eid[e] * NH + h] = a;
            }
            __syncthreads();
            for (int e = 0; e < clen; e++)
                acc += s_exp[e * NH + hc] * g_value[(size_t)t_src[e] * MD + tid];
            __syncthreads();
        }
        out[(size_t)n * MD + tid] += acc;
    }
}

// ---------------- launch -----------------------------------------------------
extern "C" void kernel_launch(void* const* d_in, const int* in_sizes, int n_in,
                              void* d_out, int out_size) {
    const float* inp   = (const float*)d_in[0];
    const int*   ei    = (const int*)d_in[1];
    const float* dist  = (const float*)d_in[2];
    // d_in[3] = deparc_edge (unused by reference math)
    const float* Wv    = (const float*)d_in[4];
    const float* ws    = (const float*)d_in[5];
    const float* wt    = (const float*)d_in[6];
    const float* Wself = (const float*)d_in[7];
    const float* bias  = (const float*)d_in[8];

    int N = in_sizes[0] / MD;
    int E = in_sizes[2];

    float* out  = (float*)d_out;
    float* attn = nullptr;
    if ((long long)out_size >= (long long)N * MD + (long long)E * NH)
        attn = out + (size_t)N * MD;

    k_init<<<(N + 255) / 256, 256>>>(N);
    k_node<<<(N + 15) / 16, 128>>>(inp, Wv, ws, wt, Wself, bias, out, N);
    k_edge_hist_max<<<1184, 256>>>(ei, E);
    k_scan<<<1, 1024>>>(N);
    k_scatter<<<1184, 256>>>(ei, E);
    k_aggregate<<<N, 128>>>(dist, out, attn, N);
}

// round 8
// speedup vs baseline: 1.5978x; 1.5978x over previous
#include <cuda_runtime.h>
#include <cstdint>

#define MD   128
#define NH   8
#define DV   16
#define NMAX 50000
#define EMAX 1600000
#define CAP  256
#define TMN  32
#define SB   512

typedef unsigned long long ull;

// ---------------- scratch (static device arrays; no cudaMalloc) -------------
__device__ float g_value[(size_t)NMAX * MD];   // [N,128] value projection
__device__ float g_vsrc[NMAX * NH];            // [N,8]
__device__ float g_vtgt[NMAX * NH];            // [N,8]
__device__ int   g_cnt[NMAX];                  // in-degree histogram
__device__ int   g_off[NMAX + 1];              // CSR offsets (exclusive scan)
__device__ int   g_cursor[NMAX];               // scatter cursors
__device__ int   g_csr_src[EMAX];              // src node per CSR slot
__device__ int   g_csr_eid[EMAX];              // original edge id per CSR slot
__device__ int   g_bsum[1024];                 // scan block sums
__device__ int   g_bpre[1024];                 // scan block prefixes

// ---------------- K0: reset histogram ---------------------------------------
__global__ void k_init(int N) {
    int i = blockIdx.x * blockDim.x + threadIdx.x;
    if (i < N) g_cnt[i] = 0;
}

// ---------------- K1: node projections, f32x2 packed FMA --------------------
// 256 threads: group 0 (tid 0-127) -> W_value col j (+vsrc/vtgt reduce),
//              group 1 (tid 128-255) -> W_self col j (+bias -> out).
// TMN=32 nodes per block. Inner product over k as packed {even,odd} pairs.
__global__ void __launch_bounds__(256) k_node(
        const float* __restrict__ inp,
        const float* __restrict__ Wv,
        const float* __restrict__ ws,
        const float* __restrict__ wt,
        const float* __restrict__ Wself,
        const float* __restrict__ bias,
        float* __restrict__ out, int N) {
    __shared__ float A[TMN][MD];        // 16 KB, k-contiguous rows
    __shared__ float Wsh[2][128][20];   // per-kt staged 16-col chunk, padded

    const int tid = threadIdx.x;
    const int n0  = blockIdx.x * TMN;
    const int grp = tid >> 7;
    const int j   = tid & 127;

    for (int idx = tid; idx < TMN * MD; idx += 256) {
        int m = idx >> 7, k = idx & 127;
        int n = n0 + m;
        A[m][k] = (n < N) ? inp[(size_t)n * MD + k] : 0.f;
    }

    ull acc[TMN];
#pragma unroll
    for (int m = 0; m < TMN; m++) acc[m] = 0ull;

    for (int kt = 0; kt < MD; kt += 16) {
        __syncthreads();
        // stage W[:, kt:kt+16] for both matrices, coalesced LDG.128
        for (int i = tid; i < 1024; i += 256) {
            int g = i >> 9;
            int r = (i >> 2) & 127;
            int q = i & 3;
            const float* Wg = g ? Wself : Wv;
            float4 w4 = *(const float4*)&Wg[r * MD + kt + 4 * q];
            *(float4*)&Wsh[g][r][4 * q] = w4;
        }
        __syncthreads();

        ull wp[8];
#pragma unroll
        for (int q = 0; q < 8; q++)
            wp[q] = *(const ull*)&Wsh[grp][j][2 * q];

#pragma unroll
        for (int m = 0; m < TMN; m++) {
#pragma unroll
            for (int q4 = 0; q4 < 4; q4++) {
                float4 a4 = *(const float4*)&A[m][kt + 4 * q4];
                ull alo, ahi;
                asm("mov.b64 %0, {%1,%2};" : "=l"(alo) : "f"(a4.x), "f"(a4.y));
                asm("mov.b64 %0, {%1,%2};" : "=l"(ahi) : "f"(a4.z), "f"(a4.w));
                asm("fma.rn.f32x2 %0, %1, %2, %3;"
                    : "=l"(acc[m]) : "l"(alo), "l"(wp[2 * q4]), "l"(acc[m]));
                asm("fma.rn.f32x2 %0, %1, %2, %3;"
                    : "=l"(acc[m]) : "l"(ahi), "l"(wp[2 * q4 + 1]), "l"(acc[m]));
            }
        }
    }

    const int h = j >> 4, d = j & 15;
    float wsj = 0.f, wtj = 0.f, bj = 0.f;
    if (grp == 0) { wsj = ws[j]; wtj = wt[j]; }
    else          { bj = bias[j]; }

#pragma unroll
    for (int m = 0; m < TMN; m++) {
        int n = n0 + m;
        float lo, hi;
        asm("mov.b64 {%0,%1}, %2;" : "=f"(lo), "=f"(hi) : "l"(acc[m]));
        float v = lo + hi;
        if (grp == 0) {
            if (n < N) g_value[(size_t)n * MD + j] = v;
            float t1 = v * wsj;
            float t2 = v * wtj;
#pragma unroll
            for (int o = 8; o > 0; o >>= 1) {
                t1 += __shfl_xor_sync(0xffffffffu, t1, o);
                t2 += __shfl_xor_sync(0xffffffffu, t2, o);
            }
            if (d == 0 && n < N) {
                g_vsrc[n * NH + h] = t1;
                g_vtgt[n * NH + h] = t2;
            }
        } else {
            if (n < N) out[(size_t)n * MD + j] = v + bj;
        }
    }
}

// ---------------- K2: in-degree histogram (tgt row only) --------------------
__global__ void k_hist(const int* __restrict__ ei, int E) {
    int e = blockIdx.x * blockDim.x + threadIdx.x;
    if (e < E) atomicAdd(&g_cnt[ei[E + e]], 1);
}

// ---------------- K3a/b/c: multi-block exclusive scan -----------------------
__global__ void k_scan1(int N) {
    __shared__ int sh[SB];
    int tid = threadIdx.x;
    int i = blockIdx.x * SB + tid;
    int v = (i < N) ? g_cnt[i] : 0;
    sh[tid] = v;
    __syncthreads();
    for (int o = 1; o < SB; o <<= 1) {
        int t = (tid >= o) ? sh[tid - o] : 0;
        __syncthreads();
        sh[tid] += t;
        __syncthreads();
    }
    if (i < N) g_off[i] = sh[tid] - v;          // block-local exclusive
    if (tid == SB - 1) g_bsum[blockIdx.x] = sh[SB - 1];
}

__global__ void k_scan2(int nb, int N) {
    __shared__ int sh[1024];
    int tid = threadIdx.x;
    int v = (tid < nb) ? g_bsum[tid] : 0;
    sh[tid] = v;
    __syncthreads();
    for (int o = 1; o < 1024; o <<= 1) {
        int t = (tid >= o) ? sh[tid - o] : 0;
        __syncthreads();
        sh[tid] += t;
        __syncthreads();
    }
    if (tid < nb) g_bpre[tid] = sh[tid] - v;
    if (tid == 1023) g_off[N] = sh[1023];
}

__global__ void k_scan3(int N) {
    int i = blockIdx.x * SB + threadIdx.x;
    if (i < N) {
        int o = g_off[i] + g_bpre[blockIdx.x];
        g_off[i] = o;
        g_cursor[i] = o;
    }
}

// ---------------- K4: scatter edges into CSR --------------------------------
__global__ void k_scatter(const int* __restrict__ ei, int E) {
    int e = blockIdx.x * blockDim.x + threadIdx.x;
    if (e < E) {
        int s = ei[e];
        int t = ei[E + e];
        int p = atomicAdd(&g_cursor[t], 1);
        g_csr_src[p] = s;
        g_csr_eid[p] = e;
    }
}

// ---------------- K5: per-target softmax + renorm + aggregation -------------
// Final attn = (exp(lrelu(s) - local_max)/dist) / sum_edges(...) — the
// reference's global max and (denom+eps) divide out exactly.
__global__ void k_aggregate(const float* __restrict__ dist,
                            float* __restrict__ out,
                            float* __restrict__ attn_out,
                            int N) {
    int n   = blockIdx.x;
    int tid = threadIdx.x;
    int base = g_off[n];
    int deg  = g_off[n + 1] - base;
    if (deg == 0) return;

    __shared__ float s_vtgt[NH];
    __shared__ float s_mx[NH], s_asum[NH];
    __shared__ float s_part[128];
    __shared__ float s_exp[CAP * NH];
    __shared__ int   s_src[CAP], s_eid[CAP];
    __shared__ int   t_src[CAP], t_eid[CAP];
    __shared__ float s_dist[CAP];

    if (tid < NH) s_vtgt[tid] = g_vtgt[n * NH + tid];
    int h  = tid & 7;    // head in (edge,head)-strided loops
    int hc = tid >> 4;   // head of this output column

    if (deg <= CAP) {
        for (int i = tid; i < deg; i += 128) {
            s_src[i] = g_csr_src[base + i];
            s_eid[i] = g_csr_eid[base + i];
        }
        __syncthreads();
        // deterministic rank-sort by original edge id
        for (int i = tid; i < deg; i += 128) {
            int key = s_eid[i];
            int r = 0;
            for (int q = 0; q < deg; q++) r += (s_eid[q] < key);
            t_eid[r] = key;
            t_src[r] = s_src[i];
        }
        __syncthreads();
        for (int i = tid; i < deg; i += 128) s_dist[i] = dist[t_eid[i]];
        __syncthreads();

        // pass1: scores + per-head max
        float mloc = -1e30f;
        for (int idx = tid; idx < deg * NH; idx += 128) {
            int e = idx >> 3;
            float s = g_vsrc[t_src[e] * NH + h] + s_vtgt[h];
            s = s > 0.f ? s : 0.2f * s;
            s_exp[idx] = s;
            mloc = fmaxf(mloc, s);
        }
        s_part[tid] = mloc;
        __syncthreads();
        if (tid < NH) {
            float v = -1e30f;
#pragma unroll
            for (int k = 0; k < 16; k++) v = fmaxf(v, s_part[tid + 8 * k]);
            s_mx[tid] = v;
        }
        __syncthreads();

        // pass2: w = exp(s - m)/dist, per-head sum
        float aloc = 0.f;
        for (int idx = tid; idx < deg * NH; idx += 128) {
            int e = idx >> 3;
            float w = __expf(s_exp[idx] - s_mx[h]) / s_dist[e];
            s_exp[idx] = w;
            aloc += w;
        }
        s_part[tid] = aloc;
        __syncthreads();
        if (tid < NH) {
            float v = 0.f;
#pragma unroll
            for (int k = 0; k < 16; k++) v += s_part[tid + 8 * k];
            s_asum[tid] = v;
        }
        __syncthreads();

        // pass3: normalize + write attn at original edge positions
        for (int idx = tid; idx < deg * NH; idx += 128) {
            int e = idx >> 3;
            float a = s_exp[idx] / s_asum[h];
            s_exp[idx] = a;
            if (attn_out) attn_out[(size_t)t_eid[e] * NH + h] = a;
        }
        __syncthreads();

        // pass4: weighted aggregation (thread = output column)
        float acc = 0.f;
#pragma unroll 4
        for (int e = 0; e < deg; e++)
            acc += s_exp[e * NH + hc] * g_value[(size_t)t_src[e] * MD + tid];
        out[(size_t)n * MD + tid] += acc;
    } else {
        // ---- fallback (deg > CAP): recompute-based, chunked ----
        __syncthreads();
        float mloc = -1e30f;
        for (int idx = tid; idx < deg * NH; idx += 128) {
            int e = idx >> 3;
            float s = g_vsrc[g_csr_src[base + e] * NH + h] + s_vtgt[h];
            s = s > 0.f ? s : 0.2f * s;
            mloc = fmaxf(mloc, s);
        }
        s_part[tid] = mloc;
        __syncthreads();
        if (tid < NH) {
            float v = -1e30f;
            for (int k = 0; k < 16; k++) v = fmaxf(v, s_part[tid + 8 * k]);
            s_mx[tid] = v;
        }
        __syncthreads();
        float aloc = 0.f;
        for (int idx = tid; idx < deg * NH; idx += 128) {
            int e = idx >> 3;
            float s = g_vsrc[g_csr_src[base + e] * NH + h] + s_vtgt[h];
            s = s > 0.f ? s : 0.2f * s;
            aloc += __expf(s - s_mx[h]) / dist[g_csr_eid[base + e]];
        }
        s_part[tid] = aloc;
        __syncthreads();
        if (tid < NH) {
            float v = 0.f;
            for (int k = 0; k < 16; k++) v += s_part[tid + 8 * k];
            s_asum[tid] = v;
        }
        __syncthreads();
        float acc = 0.f;
        for (int c0 = 0; c0 < deg; c0 += CAP) {
            int clen = min(CAP, deg - c0);
            for (int i = tid; i < clen; i += 128) {
                t_src[i] = g_csr_src[base + c0 + i];
                t_eid[i] = g_csr_eid[base + c0 + i];
            }
            __syncthreads();
            for (int i = tid; i < clen; i += 128) s_dist[i] = dist[t_eid[i]];
            __syncthreads();
            for (int idx = tid; idx < clen * NH; idx += 128) {
                int e = idx >> 3;
                float s = g_vsrc[t_src[e] * NH + h] + s_vtgt[h];
                s = s > 0.f ? s : 0.2f * s;
                float a = __expf(s - s_mx[h]) / s_dist[e] / s_asum[h];
                s_exp[idx] = a;
                if (attn_out) attn_out[(size_t)t_eid[e] * NH + h] = a;
            }
            __syncthreads();
            for (int e = 0; e < clen; e++)
                acc += s_exp[e * NH + hc] * g_value[(size_t)t_src[e] * MD + tid];
            __syncthreads();
        }
        out[(size_t)n * MD + tid] += acc;
    }
}

// ---------------- launch -----------------------------------------------------
extern "C" void kernel_launch(void* const* d_in, const int* in_sizes, int n_in,
                              void* d_out, int out_size) {
    const float* inp   = (const float*)d_in[0];
    const int*   ei    = (const int*)d_in[1];
    const float* dist  = (const float*)d_in[2];
    // d_in[3] = deparc_edge (unused by the reference math)
    const float* Wv    = (const float*)d_in[4];
    const float* ws    = (const float*)d_in[5];
    const float* wt    = (const float*)d_in[6];
    const float* Wself = (const float*)d_in[7];
    const float* bias  = (const float*)d_in[8];

    int N = in_sizes[0] / MD;
    int E = in_sizes[2];
    int nb = (N + SB - 1) / SB;

    float* out  = (float*)d_out;
    float* attn = nullptr;
    if ((long long)out_size >= (long long)N * MD + (long long)E * NH)
        attn = out + (size_t)N * MD;

    k_init<<<(N + 255) / 256, 256>>>(N);
    k_node<<<(N + TMN - 1) / TMN, 256>>>(inp, Wv, ws, wt, Wself, bias, out, N);
    k_hist<<<(E + 255) / 256, 256>>>(ei, E);
    k_scan1<<<nb, SB>>>(N);
    k_scan2<<<1, 1024>>>(nb, N);
    k_scan3<<<nb, SB>>>(N);
    k_scatter<<<(E + 255) / 256, 256>>>(ei, E);
    k_aggregate<<<N, 128>>>(dist, out, attn, N);
}